// round 8
// baseline (speedup 1.0000x reference)
#include <cuda_runtime.h>
#include <math.h>

// Problem constants
constexpr int T  = 2048;
constexpr int B  = 64;
constexpr int H  = 128;
constexpr int G  = 512;   // 4*H gate rows
constexpr int IN = 128;

typedef unsigned long long u64;

// ---------------------------------------------------------------------------
// Scratch (static __device__ arrays — no allocation in kernel_launch)
// ---------------------------------------------------------------------------
__device__ float g_xp[(size_t)T * B * G];   // 256 MB: xproj (+bias) per timestep
__device__ float g_hs[(size_t)T * B * H];   // 64 MB: layer-0 hidden states
__device__ float g_hT[B * H];               // final hidden of layer 1

// ---------------------------------------------------------------------------
// Packed fp32x2 helpers (PTX ISA 8.6+, sm_100+)
// ---------------------------------------------------------------------------
__device__ __forceinline__ u64 ffma2(u64 a, u64 b, u64 c) {
    u64 d;
    asm("fma.rn.f32x2 %0, %1, %2, %3;" : "=l"(d) : "l"(a), "l"(b), "l"(c));
    return d;
}
__device__ __forceinline__ u64 pack_dup(float a) {
    u64 d; asm("mov.b64 %0, {%1, %1};" : "=l"(d) : "f"(a)); return d;
}
__device__ __forceinline__ u64 pack2(float x, float y) {
    u64 d; asm("mov.b64 %0, {%1, %2};" : "=l"(d) : "f"(x), "f"(y)); return d;
}
__device__ __forceinline__ float2 unpack2(u64 a) {
    float2 r; asm("mov.b64 {%0, %1}, %2;" : "=f"(r.x), "=f"(r.y) : "l"(a)); return r;
}
__device__ __forceinline__ float hadd2(u64 a) {
    float2 r = unpack2(a); return r.x + r.y;
}

// Fast transcendentals (validated: rel_err ~6e-7 end-to-end)
__device__ __forceinline__ float sigf(float x) {
    return __fdividef(1.f, 1.f + __expf(-x));
}
__device__ __forceinline__ float tanh_fast(float x) {
    return 1.f - __fdividef(2.f, __expf(2.f * x) + 1.f);
}

// ---------------------------------------------------------------------------
// Kernel: input projection GEMM, 16 timesteps per CTA (W tile stays resident,
// 4x fewer CTAs/waves than TT=4). Grid (T/16, 8), 256 threads.
// Tile 64(b) x 64(g), K=128.
// ---------------------------------------------------------------------------
constexpr int TT = 16;                        // timesteps per CTA
constexpr int GEMM_SMEM = (128 * 68 + 64 * 136) * 4;   // Ws + As = 69,632 B

template<int LAYER>
__global__ __launch_bounds__(256)
void xproj_gemm(const float* __restrict__ mapf, const float* __restrict__ pos,
                const float* __restrict__ Wih,  const float* __restrict__ bih,
                const float* __restrict__ bhh)
{
    extern __shared__ float sm[];
    float* Ws = sm;               // [128][68] k-major: Ws[k*68 + g]
    float* As = sm + 128 * 68;    // [64][136] row-major: As[b*136 + k]

    const int t0  = blockIdx.x * TT;
    const int gc  = blockIdx.y;
    const int tid = threadIdx.x;

    // Load W tile once (reused for TT timesteps)
    for (int idx = tid; idx < 64 * 128; idx += 256) {
        const int k = idx & 127;
        const int g = idx >> 7;
        Ws[k * 68 + g] = Wih[(gc * 64 + g) * IN + k];
    }

    const int bb   = tid >> 3;   // 0..31 (also handles bb+32)
    const int gblk = tid & 7;
    const int gbase = gc * 64 + gblk * 8;
    float bias[8];
    #pragma unroll
    for (int i = 0; i < 8; i++) bias[i] = bih[gbase + i] + bhh[gbase + i];

    for (int tt = 0; tt < TT; tt++) {
        const int t = t0 + tt;
        __syncthreads();   // protects As reuse (and Ws on first pass)
        for (int idx = tid; idx < 64 * 128; idx += 256) {
            const int k = idx & 127;
            const int r = idx >> 7;
            float v;
            if (LAYER == 0) {
                v = (k < 126) ? mapf[((size_t)r * T + t) * 126 + k]
                              : pos[((size_t)r * T + t) * 2 + (k - 126)];
            } else {
                v = g_hs[((size_t)t * B + r) * H + k];
            }
            As[r * 136 + k] = v;
        }
        __syncthreads();

        u64 acc[8];
        #pragma unroll
        for (int i = 0; i < 8; i++) acc[i] = 0ull;

        #pragma unroll 8
        for (int k = 0; k < 128; k++) {
            const u64 a0 = pack_dup(As[bb * 136 + k]);
            const u64 a1 = pack_dup(As[(bb + 32) * 136 + k]);
            const ulonglong2* wp = (const ulonglong2*)&Ws[k * 68 + gblk * 8];
            const ulonglong2 wlo = wp[0], whi = wp[1];
            acc[0] = ffma2(wlo.x, a0, acc[0]);
            acc[1] = ffma2(wlo.y, a0, acc[1]);
            acc[2] = ffma2(whi.x, a0, acc[2]);
            acc[3] = ffma2(whi.y, a0, acc[3]);
            acc[4] = ffma2(wlo.x, a1, acc[4]);
            acc[5] = ffma2(wlo.y, a1, acc[5]);
            acc[6] = ffma2(whi.x, a1, acc[6]);
            acc[7] = ffma2(whi.y, a1, acc[7]);
        }

        #pragma unroll
        for (int half = 0; half < 2; half++) {
            const int row = bb + half * 32;
            float4 o0, o1;
            float2 p0 = unpack2(acc[half * 4 + 0]);
            float2 p1 = unpack2(acc[half * 4 + 1]);
            float2 p2 = unpack2(acc[half * 4 + 2]);
            float2 p3 = unpack2(acc[half * 4 + 3]);
            o0.x = p0.x + bias[0]; o0.y = p0.y + bias[1];
            o0.z = p1.x + bias[2]; o0.w = p1.y + bias[3];
            o1.x = p2.x + bias[4]; o1.y = p2.y + bias[5];
            o1.z = p3.x + bias[6]; o1.w = p3.y + bias[7];
            float* op = g_xp + ((size_t)t * B + row) * G + gbase;
            ((float4*)op)[0] = o0;
            ((float4*)op)[1] = o1;
        }
    }
}

// ---------------------------------------------------------------------------
// Kernel: persistent LSTM recurrence. One CTA per batch row, 256 threads,
// TWO gate rows per thread (rows tid and 256+tid). Cols 0..83 of both rows in
// registers (42 u64 each); cols 84..127 in smem as ulonglong2 (11 per row).
// Dot loop is pure LDS.128 -> FFMA2 (no repack MOVs): h read as ulonglong2
// (broadcast), weights read as ulonglong2. Gates exchanged as one packed u64
// per thread. rows 0..127=i, 128..255=f (sigmoid); 256..383=g (tanh), 384..511=o.
// ---------------------------------------------------------------------------
constexpr int REC_SMEM = 11 * 2 * 256 * 16 + 128 * 4 + 256 * 8;  // wsm + hbuf + gates2

template<bool WRITE_ALL>
__global__ __launch_bounds__(256, 1)
void lstm_rec(const float* __restrict__ Whh)
{
    extern __shared__ float sm[];
    ulonglong2* wsmq = (ulonglong2*)sm;                 // [(q*2+half)*256 + tid], q=0..10
    float*      hbuf = (float*)(sm) + 11 * 2 * 256 * 4; // 128 floats (16B aligned)
    u64*        gates2 = (u64*)(hbuf + 128);            // 256 packed gate pairs

    const int tid  = threadIdx.x;
    const int b    = blockIdx.x;
    const int rowA = tid;         // i (tid<128) or f gate
    const int rowB = 256 + tid;   // g (tid<128) or o gate

    // Register-resident weights: cols 0..83 of both rows (42 u64 each)
    u64 wrA[42], wrB[42];
    {
        const u64* pa = (const u64*)(Whh + rowA * IN);
        const u64* pb = (const u64*)(Whh + rowB * IN);
        #pragma unroll
        for (int i = 0; i < 42; i++) { wrA[i] = pa[i]; wrB[i] = pb[i]; }
    }
    // Tail cols 84..127 (11 ulonglong2 per row) to smem
    {
        const ulonglong2* ta = (const ulonglong2*)(Whh + rowA * IN + 84);
        const ulonglong2* tb = (const ulonglong2*)(Whh + rowB * IN + 84);
        #pragma unroll
        for (int q = 0; q < 11; q++) {
            wsmq[(q * 2 + 0) * 256 + tid] = ta[q];
            wsmq[(q * 2 + 1) * 256 + tid] = tb[q];
        }
    }
    if (tid < H) hbuf[tid] = 0.f;
    float c = 0.f;

    const float* xpb = g_xp + (size_t)b * G;
    float xa = xpb[rowA];
    float xb = xpb[rowB];
    const bool tanhB = (tid < 128);   // rowB in g-gate range
    __syncthreads();

    #pragma unroll 1
    for (int t = 0; t < T; t++) {
        const ulonglong2* hbq = (const ulonglong2*)hbuf;   // 32 entries
        u64 a0 = 0ull, a1 = 0ull, b0 = 0ull, b1 = 0ull;
        // cols 0..83 from registers (21 ulonglong2 of h)
        #pragma unroll
        for (int q = 0; q < 21; q++) {
            const ulonglong2 hv = hbq[q];
            a0 = ffma2(wrA[2 * q],     hv.x, a0);
            a1 = ffma2(wrA[2 * q + 1], hv.y, a1);
            b0 = ffma2(wrB[2 * q],     hv.x, b0);
            b1 = ffma2(wrB[2 * q + 1], hv.y, b1);
        }
        // cols 84..127 from smem (11 ulonglong2 per row)
        #pragma unroll
        for (int q = 0; q < 11; q++) {
            const ulonglong2 hv = hbq[21 + q];
            const ulonglong2 wa = wsmq[(q * 2 + 0) * 256 + tid];
            const ulonglong2 wb = wsmq[(q * 2 + 1) * 256 + tid];
            a0 = ffma2(wa.x, hv.x, a0);
            a1 = ffma2(wa.y, hv.y, a1);
            b0 = ffma2(wb.x, hv.x, b0);
            b1 = ffma2(wb.y, hv.y, b1);
        }
        const float aA = hadd2(a0) + hadd2(a1) + xa;
        const float aB = hadd2(b0) + hadd2(b1) + xb;
        const float actA = sigf(aA);                              // i or f
        const float actB = tanhB ? tanh_fast(aB) : sigf(aB);      // g or o
        // prefetch next step's xproj (hidden behind next dot)
        if (t + 1 < T) {
            const float* nx = xpb + (size_t)(t + 1) * (B * G);
            xa = nx[rowA];
            xb = nx[rowB];
        }
        gates2[tid] = pack2(actA, actB);    // (i,g) for tid<128, (f,o) else
        __syncthreads();
        if (tid < H) {
            const float2 ig_gg = unpack2(gates2[tid]);        // (i, g)
            const float2 fg_og = unpack2(gates2[tid + 128]);  // (f, o)
            c = fg_og.x * c + ig_gg.x * ig_gg.y;
            const float h = fg_og.y * tanh_fast(c);
            hbuf[tid] = h;
            if (WRITE_ALL) {
                g_hs[((size_t)t * B + b) * H + tid] = h;
            } else if (t == T - 1) {
                g_hT[b * H + tid] = h;
            }
        }
        __syncthreads();
    }
}

// ---------------------------------------------------------------------------
// MLP head: one CTA per batch row, 64 threads.
// ---------------------------------------------------------------------------
__global__ void head_kernel(const float* __restrict__ W1, const float* __restrict__ b1,
                            const float* __restrict__ lng, const float* __restrict__ lnb,
                            const float* __restrict__ W2, const float* __restrict__ b2,
                            float* __restrict__ out)
{
    __shared__ float hb[128];
    __shared__ float red[64];
    __shared__ float bc;
    const int b = blockIdx.x;
    const int j = threadIdx.x;

    hb[j]      = g_hT[b * H + j];
    hb[j + 64] = g_hT[b * H + 64 + j];
    __syncthreads();

    float acc = b1[j];
    #pragma unroll 8
    for (int k = 0; k < H; k++) acc += hb[k] * W1[j * H + k];

    red[j] = acc; __syncthreads();
    if (j == 0) { float s = 0.f; for (int k = 0; k < 64; k++) s += red[k]; bc = s * (1.f / 64.f); }
    __syncthreads();
    const float mu = bc;
    const float d  = acc - mu;

    red[j] = d * d; __syncthreads();
    if (j == 0) { float s = 0.f; for (int k = 0; k < 64; k++) s += red[k]; bc = s * (1.f / 64.f); }
    __syncthreads();
    const float var = bc;

    float v = d * rsqrtf(var + 1e-5f) * lng[j] + lnb[j];
    v = (v >= 0.f) ? v : 0.2f * v;

    red[j] = v * W2[j]; __syncthreads();
    if (j == 0) { float s = 0.f; for (int k = 0; k < 64; k++) s += red[k]; out[b] = s + b2[0]; }
}

// ---------------------------------------------------------------------------
// Launch: gemm0 -> rec0 -> gemm1 -> rec1 -> head
// ---------------------------------------------------------------------------
extern "C" void kernel_launch(void* const* d_in, const int* in_sizes, int n_in,
                              void* d_out, int out_size)
{
    const float* mapf = (const float*)d_in[0];
    const float* pos  = (const float*)d_in[1];
    const float* Wih0 = (const float*)d_in[2];
    const float* Whh0 = (const float*)d_in[3];
    const float* bih0 = (const float*)d_in[4];
    const float* bhh0 = (const float*)d_in[5];
    const float* Wih1 = (const float*)d_in[6];
    const float* Whh1 = (const float*)d_in[7];
    const float* bih1 = (const float*)d_in[8];
    const float* bhh1 = (const float*)d_in[9];
    const float* W1   = (const float*)d_in[10];
    const float* b1   = (const float*)d_in[11];
    const float* lng  = (const float*)d_in[12];
    const float* lnb  = (const float*)d_in[13];
    const float* W2   = (const float*)d_in[14];
    const float* b2   = (const float*)d_in[15];
    float* out = (float*)d_out;

    cudaFuncSetAttribute((const void*)xproj_gemm<0>,
                         cudaFuncAttributeMaxDynamicSharedMemorySize, GEMM_SMEM);
    cudaFuncSetAttribute((const void*)xproj_gemm<1>,
                         cudaFuncAttributeMaxDynamicSharedMemorySize, GEMM_SMEM);
    cudaFuncSetAttribute((const void*)lstm_rec<true>,
                         cudaFuncAttributeMaxDynamicSharedMemorySize, REC_SMEM);
    cudaFuncSetAttribute((const void*)lstm_rec<false>,
                         cudaFuncAttributeMaxDynamicSharedMemorySize, REC_SMEM);

    dim3 gg(T / TT, 8);
    xproj_gemm<0><<<gg, 256, GEMM_SMEM>>>(mapf, pos, Wih0, bih0, bhh0);
    lstm_rec<true><<<B, 256, REC_SMEM>>>(Whh0);
    xproj_gemm<1><<<gg, 256, GEMM_SMEM>>>(mapf, pos, Wih1, bih1, bhh1);
    lstm_rec<false><<<B, 256, REC_SMEM>>>(Whh1);
    head_kernel<<<B, 64>>>(W1, b1, lng, lnb, W2, b2, out);
}

// round 10
// speedup vs baseline: 1.2274x; 1.2274x over previous
#include <cuda_runtime.h>
#include <math.h>

// Problem constants
constexpr int T  = 2048;
constexpr int B  = 64;
constexpr int H  = 128;
constexpr int G  = 512;   // 4*H gate rows
constexpr int IN = 128;

constexpr int CH     = 128;      // producer/consumer chunk (timesteps)
constexpr int NCHUNK = T / CH;   // 16
constexpr int NG     = 80;       // gemm CTAs inside fused kernel (10 per gc)
constexpr int RECC   = 64;       // rec CTAs (one per batch row)

typedef unsigned long long u64;

// ---------------------------------------------------------------------------
// Scratch (static __device__ arrays — no allocation in kernel_launch)
// ---------------------------------------------------------------------------
__device__ float g_xp0[(size_t)T * B * G];  // layer-0 input projections (+bias)
__device__ float g_xp1[(size_t)T * B * G];  // layer-1 input projections (+bias)
__device__ float g_hs[(size_t)T * B * H];   // layer-0 hidden states
__device__ float g_hT[B * H];               // final hidden of layer 1
__device__ int   g_h0_done;                 // rec0 progress: 64 * chunks_done

__global__ void reset_flags() { g_h0_done = 0; }

// ---------------------------------------------------------------------------
// Packed fp32x2 helpers (PTX ISA 8.6+, sm_100+)
// ---------------------------------------------------------------------------
__device__ __forceinline__ u64 ffma2(u64 a, u64 b, u64 c) {
    u64 d;
    asm("fma.rn.f32x2 %0, %1, %2, %3;" : "=l"(d) : "l"(a), "l"(b), "l"(c));
    return d;
}
__device__ __forceinline__ u64 pack_dup(float a) {
    u64 d; asm("mov.b64 %0, {%1, %1};" : "=l"(d) : "f"(a)); return d;
}
__device__ __forceinline__ u64 pack2(float x, float y) {
    u64 d; asm("mov.b64 %0, {%1, %2};" : "=l"(d) : "f"(x), "f"(y)); return d;
}
__device__ __forceinline__ float2 unpack2(u64 a) {
    float2 r; asm("mov.b64 {%0, %1}, %2;" : "=f"(r.x), "=f"(r.y) : "l"(a)); return r;
}
__device__ __forceinline__ float hadd2(u64 a) {
    float2 r = unpack2(a); return r.x + r.y;
}
__device__ __forceinline__ float sigf(float x) {
    return __fdividef(1.f, 1.f + __expf(-x));
}
__device__ __forceinline__ float tanh_fast(float x) {
    return 1.f - __fdividef(2.f, __expf(2.f * x) + 1.f);
}

// ---------------------------------------------------------------------------
// Shared building block: LSTM recurrence (device inline).
// Rec CTA layout: 256 threads, thread owns gate rows (tid, 256+tid).
// Cols 0..83 in regs (42 u64 per row), cols 84..127 in smem (11 ulonglong2).
// ---------------------------------------------------------------------------
constexpr int REC_SMEM = 11 * 2 * 256 * 16 + 128 * 4 + 256 * 8;  // 92,672 B

template<bool WRITE_ALL, bool PUBLISH>
__device__ __forceinline__ void rec_body(const float* __restrict__ Whh,
                                         const float* __restrict__ xp,
                                         float* smbase, int b)
{
    ulonglong2* wsmq = (ulonglong2*)smbase;                   // 11*2*256 entries
    float*      hbuf = smbase + 11 * 2 * 256 * 4;             // 128 floats
    u64*        gates2 = (u64*)(hbuf + 128);                  // 256 packed pairs

    const int tid  = threadIdx.x;
    const int rowA = tid;
    const int rowB = 256 + tid;

    u64 wrA[42], wrB[42];
    {
        const u64* pa = (const u64*)(Whh + rowA * IN);
        const u64* pb = (const u64*)(Whh + rowB * IN);
        #pragma unroll
        for (int i = 0; i < 42; i++) { wrA[i] = pa[i]; wrB[i] = pb[i]; }
    }
    {
        const ulonglong2* ta = (const ulonglong2*)(Whh + rowA * IN + 84);
        const ulonglong2* tb = (const ulonglong2*)(Whh + rowB * IN + 84);
        #pragma unroll
        for (int q = 0; q < 11; q++) {
            wsmq[(q * 2 + 0) * 256 + tid] = ta[q];
            wsmq[(q * 2 + 1) * 256 + tid] = tb[q];
        }
    }
    if (tid < H) hbuf[tid] = 0.f;
    float c = 0.f;

    const float* xpb = xp + (size_t)b * G;
    float xa = xpb[rowA];
    float xb = xpb[rowB];
    const bool tanhB = (tid < 128);
    __syncthreads();

    #pragma unroll 1
    for (int t = 0; t < T; t++) {
        const ulonglong2* hbq = (const ulonglong2*)hbuf;
        u64 a0 = 0ull, a1 = 0ull, b0 = 0ull, b1 = 0ull;
        #pragma unroll
        for (int q = 0; q < 21; q++) {
            const ulonglong2 hv = hbq[q];
            a0 = ffma2(wrA[2 * q],     hv.x, a0);
            a1 = ffma2(wrA[2 * q + 1], hv.y, a1);
            b0 = ffma2(wrB[2 * q],     hv.x, b0);
            b1 = ffma2(wrB[2 * q + 1], hv.y, b1);
        }
        #pragma unroll
        for (int q = 0; q < 11; q++) {
            const ulonglong2 hv = hbq[21 + q];
            const ulonglong2 wa = wsmq[(q * 2 + 0) * 256 + tid];
            const ulonglong2 wb = wsmq[(q * 2 + 1) * 256 + tid];
            a0 = ffma2(wa.x, hv.x, a0);
            a1 = ffma2(wa.y, hv.y, a1);
            b0 = ffma2(wb.x, hv.x, b0);
            b1 = ffma2(wb.y, hv.y, b1);
        }
        const float aA = hadd2(a0) + hadd2(a1) + xa;
        const float aB = hadd2(b0) + hadd2(b1) + xb;
        const float actA = sigf(aA);
        const float actB = tanhB ? tanh_fast(aB) : sigf(aB);
        if (t + 1 < T) {
            const float* nx = xpb + (size_t)(t + 1) * (B * G);
            xa = nx[rowA];
            xb = nx[rowB];
        }
        gates2[tid] = pack2(actA, actB);
        __syncthreads();
        if (tid < H) {
            const float2 ig_gg = unpack2(gates2[tid]);
            const float2 fg_og = unpack2(gates2[tid + 128]);
            c = fg_og.x * c + ig_gg.x * ig_gg.y;
            const float h = fg_og.y * tanh_fast(c);
            hbuf[tid] = h;
            if (WRITE_ALL) {
                g_hs[((size_t)t * B + b) * H + tid] = h;
            } else if (t == T - 1) {
                g_hT[b * H + tid] = h;
            }
        }
        __syncthreads();
        if (PUBLISH && ((t & (CH - 1)) == CH - 1)) {
            __threadfence();          // release: chunk's g_hs visible chip-wide
            __syncthreads();          // all threads' fences retired
            if (tid == 0) atomicAdd(&g_h0_done, 1);
        }
    }
}

// ---------------------------------------------------------------------------
// GEMM tile compute (64b x 64g, K=128) from smem; shared by gemm0 and fused.
// ---------------------------------------------------------------------------
__device__ __forceinline__ void gemm_tile(const float* Ws, const float* As,
                                          const float* bias, float* outp)
{
    const int tid  = threadIdx.x;
    const int bb   = tid >> 3;
    const int gblk = tid & 7;

    u64 acc[8];
    #pragma unroll
    for (int i = 0; i < 8; i++) acc[i] = 0ull;

    #pragma unroll 8
    for (int k = 0; k < 128; k++) {
        const u64 a0 = pack_dup(As[bb * 136 + k]);
        const u64 a1 = pack_dup(As[(bb + 32) * 136 + k]);
        const ulonglong2* wp = (const ulonglong2*)&Ws[k * 68 + gblk * 8];
        const ulonglong2 wlo = wp[0], whi = wp[1];
        acc[0] = ffma2(wlo.x, a0, acc[0]);
        acc[1] = ffma2(wlo.y, a0, acc[1]);
        acc[2] = ffma2(whi.x, a0, acc[2]);
        acc[3] = ffma2(whi.y, a0, acc[3]);
        acc[4] = ffma2(wlo.x, a1, acc[4]);
        acc[5] = ffma2(wlo.y, a1, acc[5]);
        acc[6] = ffma2(whi.x, a1, acc[6]);
        acc[7] = ffma2(whi.y, a1, acc[7]);
    }

    #pragma unroll
    for (int half = 0; half < 2; half++) {
        const int row = bb + half * 32;
        float4 o0, o1;
        float2 p0 = unpack2(acc[half * 4 + 0]);
        float2 p1 = unpack2(acc[half * 4 + 1]);
        float2 p2 = unpack2(acc[half * 4 + 2]);
        float2 p3 = unpack2(acc[half * 4 + 3]);
        o0.x = p0.x + bias[0]; o0.y = p0.y + bias[1];
        o0.z = p1.x + bias[2]; o0.w = p1.y + bias[3];
        o1.x = p2.x + bias[4]; o1.y = p2.y + bias[5];
        o1.z = p3.x + bias[6]; o1.w = p3.y + bias[7];
        float* op = outp + (size_t)row * G;
        ((float4*)op)[0] = o0;
        ((float4*)op)[1] = o1;
    }
}

// ---------------------------------------------------------------------------
// Kernel: layer-0 input projection GEMM, TT=4 (R7 config — best measured).
// Grid (T/4, 8), 256 threads.
// ---------------------------------------------------------------------------
constexpr int TT = 4;
constexpr int GEMM_SMEM = (128 * 68 + 64 * 136) * 4;   // Ws + As = 69,632 B

__global__ __launch_bounds__(256)
void xproj_gemm0(const float* __restrict__ mapf, const float* __restrict__ pos,
                 const float* __restrict__ Wih,  const float* __restrict__ bih,
                 const float* __restrict__ bhh)
{
    extern __shared__ float sm[];
    float* Ws = sm;               // [128][68] k-major
    float* As = sm + 128 * 68;    // [64][136] row-major

    const int t0  = blockIdx.x * TT;
    const int gc  = blockIdx.y;
    const int tid = threadIdx.x;

    for (int idx = tid; idx < 64 * 128; idx += 256) {
        const int k = idx & 127;
        const int g = idx >> 7;
        Ws[k * 68 + g] = Wih[(gc * 64 + g) * IN + k];
    }

    const int gblk = tid & 7;
    const int gbase = gc * 64 + gblk * 8;
    float bias[8];
    #pragma unroll
    for (int i = 0; i < 8; i++) bias[i] = bih[gbase + i] + bhh[gbase + i];

    for (int tt = 0; tt < TT; tt++) {
        const int t = t0 + tt;
        __syncthreads();
        for (int idx = tid; idx < 64 * 128; idx += 256) {
            const int k = idx & 127;
            const int r = idx >> 7;
            const float v = (k < 126) ? mapf[((size_t)r * T + t) * 126 + k]
                                      : pos[((size_t)r * T + t) * 2 + (k - 126)];
            As[r * 136 + k] = v;
        }
        __syncthreads();
        gemm_tile(Ws, As, bias, g_xp0 + (size_t)t * B * G + gbase);
    }
}

// ---------------------------------------------------------------------------
// FUSED kernel: rec0 (64 CTAs) + layer-1 gemm (80 persistent CTAs).
// 144 CTAs at 1 CTA/SM <= 148 SMs -> entire grid is wave 1 -> producer and
// consumer CTAs are co-resident; spin-wait cannot deadlock.
// gemm CTA (bid>=64): gc = idx&7 fixed, sub = idx>>3 (0..9); processes
// timesteps t = c*CH + sub + i*10 of chunk c once rec0 published chunk c.
// ---------------------------------------------------------------------------
__global__ __launch_bounds__(256, 1)
void fused_rec0_gemm1(const float* __restrict__ Whh0,
                      const float* __restrict__ Wih1,
                      const float* __restrict__ bih1,
                      const float* __restrict__ bhh1)
{
    extern __shared__ float sm[];
    const int tid = threadIdx.x;

    if (blockIdx.x < RECC) {
        rec_body<true, true>(Whh0, g_xp0, sm, blockIdx.x);
        return;
    }

    // ---- gemm role ----
    const int idx = blockIdx.x - RECC;   // 0..NG-1
    const int gc  = idx & 7;
    const int sub = idx >> 3;            // 0..9
    float* Ws = sm;
    float* As = sm + 128 * 68;

    for (int i = tid; i < 64 * 128; i += 256) {
        const int k = i & 127;
        const int g = i >> 7;
        Ws[k * 68 + g] = Wih1[(gc * 64 + g) * IN + k];
    }

    const int gblk = tid & 7;
    const int gbase = gc * 64 + gblk * 8;
    float bias[8];
    #pragma unroll
    for (int i = 0; i < 8; i++) bias[i] = bih1[gbase + i] + bhh1[gbase + i];

    for (int c = 0; c < NCHUNK; c++) {
        if (tid == 0) {
            const int target = RECC * (c + 1);
            while (*((volatile int*)&g_h0_done) < target) { __nanosleep(200); }
        }
        __syncthreads();
        __threadfence();   // acquire: order subsequent g_hs reads after flag

        for (int tl = sub; tl < CH; tl += 10) {
            const int t = c * CH + tl;
            __syncthreads();   // protect As from previous tile's readers
            // load As = h0[t] (64 x 128 floats) with float4 loads
            const float4* src = (const float4*)(g_hs + (size_t)t * B * H);
            #pragma unroll
            for (int j = 0; j < 8; j++) {
                const int i4 = tid + j * 256;       // 0..2047
                const int r  = i4 >> 5;
                const int k4 = i4 & 31;
                ((float4*)&As[r * 136 + k4 * 4])[0] = src[i4];
            }
            __syncthreads();
            gemm_tile(Ws, As, bias, g_xp1 + (size_t)t * B * G + gbase);
        }
    }
}

// ---------------------------------------------------------------------------
// rec1: standard recurrence over g_xp1, writes g_hT only.
// ---------------------------------------------------------------------------
__global__ __launch_bounds__(256, 1)
void lstm_rec1(const float* __restrict__ Whh)
{
    extern __shared__ float sm[];
    rec_body<false, false>(Whh, g_xp1, sm, blockIdx.x);
}

// ---------------------------------------------------------------------------
// MLP head: one CTA per batch row, 64 threads.
// ---------------------------------------------------------------------------
__global__ void head_kernel(const float* __restrict__ W1, const float* __restrict__ b1,
                            const float* __restrict__ lng, const float* __restrict__ lnb,
                            const float* __restrict__ W2, const float* __restrict__ b2,
                            float* __restrict__ out)
{
    __shared__ float hb[128];
    __shared__ float red[64];
    __shared__ float bc;
    const int b = blockIdx.x;
    const int j = threadIdx.x;

    hb[j]      = g_hT[b * H + j];
    hb[j + 64] = g_hT[b * H + 64 + j];
    __syncthreads();

    float acc = b1[j];
    #pragma unroll 8
    for (int k = 0; k < H; k++) acc += hb[k] * W1[j * H + k];

    red[j] = acc; __syncthreads();
    if (j == 0) { float s = 0.f; for (int k = 0; k < 64; k++) s += red[k]; bc = s * (1.f / 64.f); }
    __syncthreads();
    const float mu = bc;
    const float d  = acc - mu;

    red[j] = d * d; __syncthreads();
    if (j == 0) { float s = 0.f; for (int k = 0; k < 64; k++) s += red[k]; bc = s * (1.f / 64.f); }
    __syncthreads();
    const float var = bc;

    float v = d * rsqrtf(var + 1e-5f) * lng[j] + lnb[j];
    v = (v >= 0.f) ? v : 0.2f * v;

    red[j] = v * W2[j]; __syncthreads();
    if (j == 0) { float s = 0.f; for (int k = 0; k < 64; k++) s += red[k]; out[b] = s + b2[0]; }
}

// ---------------------------------------------------------------------------
// Launch: reset -> gemm0 -> fused(rec0 || gemm1) -> rec1 -> head
// ---------------------------------------------------------------------------
extern "C" void kernel_launch(void* const* d_in, const int* in_sizes, int n_in,
                              void* d_out, int out_size)
{
    const float* mapf = (const float*)d_in[0];
    const float* pos  = (const float*)d_in[1];
    const float* Wih0 = (const float*)d_in[2];
    const float* Whh0 = (const float*)d_in[3];
    const float* bih0 = (const float*)d_in[4];
    const float* bhh0 = (const float*)d_in[5];
    const float* Wih1 = (const float*)d_in[6];
    const float* Whh1 = (const float*)d_in[7];
    const float* bih1 = (const float*)d_in[8];
    const float* bhh1 = (const float*)d_in[9];
    const float* W1   = (const float*)d_in[10];
    const float* b1   = (const float*)d_in[11];
    const float* lng  = (const float*)d_in[12];
    const float* lnb  = (const float*)d_in[13];
    const float* W2   = (const float*)d_in[14];
    const float* b2   = (const float*)d_in[15];
    float* out = (float*)d_out;

    cudaFuncSetAttribute((const void*)xproj_gemm0,
                         cudaFuncAttributeMaxDynamicSharedMemorySize, GEMM_SMEM);
    cudaFuncSetAttribute((const void*)fused_rec0_gemm1,
                         cudaFuncAttributeMaxDynamicSharedMemorySize, REC_SMEM);
    cudaFuncSetAttribute((const void*)lstm_rec1,
                         cudaFuncAttributeMaxDynamicSharedMemorySize, REC_SMEM);

    reset_flags<<<1, 1>>>();
    dim3 gg(T / TT, 8);
    xproj_gemm0<<<gg, 256, GEMM_SMEM>>>(mapf, pos, Wih0, bih0, bhh0);
    fused_rec0_gemm1<<<RECC + NG, 256, REC_SMEM>>>(Whh0, Wih1, bih1, bhh1);
    lstm_rec1<<<RECC, 256, REC_SMEM>>>(Whh1);
    head_kernel<<<B, 64>>>(W1, b1, lng, lnb, W2, b2, out);
}

// round 11
// speedup vs baseline: 1.4533x; 1.1840x over previous
#include <cuda_runtime.h>
#include <math.h>

// Problem constants
constexpr int T  = 2048;
constexpr int B  = 64;
constexpr int H  = 128;
constexpr int G  = 512;   // 4*H gate rows
constexpr int IN = 128;

constexpr int CH     = 128;      // producer/consumer chunk (timesteps)
constexpr int NCHUNK = T / CH;   // 16
constexpr int RECC0  = 32;       // rec0 CTAs (2 batches each)
constexpr int NG     = 80;       // gemm CTAs (10 per gc)
constexpr int RECC1  = 32;       // rec1 CTAs (2 batches each)

typedef unsigned long long u64;

// ---------------------------------------------------------------------------
// Scratch (static __device__ arrays — no allocation in kernel_launch)
// ---------------------------------------------------------------------------
__device__ float g_xp0[(size_t)T * B * G];  // layer-0 input projections (+bias)
__device__ float g_xp1[(size_t)T * B * G];  // layer-1 input projections (+bias)
__device__ float g_hs[(size_t)T * B * H];   // layer-0 hidden states
__device__ float g_hT[B * H];               // final hidden of layer 1
__device__ int   g_h0_done;                 // rec0 progress: RECC0 * chunks
__device__ int   g_xp1_done;                // gemm progress: NG * chunks

__global__ void reset_flags() { g_h0_done = 0; g_xp1_done = 0; }

// ---------------------------------------------------------------------------
// Packed fp32x2 helpers (PTX ISA 8.6+, sm_100+)
// ---------------------------------------------------------------------------
__device__ __forceinline__ u64 ffma2(u64 a, u64 b, u64 c) {
    u64 d;
    asm("fma.rn.f32x2 %0, %1, %2, %3;" : "=l"(d) : "l"(a), "l"(b), "l"(c));
    return d;
}
__device__ __forceinline__ u64 pack_dup(float a) {
    u64 d; asm("mov.b64 %0, {%1, %1};" : "=l"(d) : "f"(a)); return d;
}
__device__ __forceinline__ u64 pack2(float x, float y) {
    u64 d; asm("mov.b64 %0, {%1, %2};" : "=l"(d) : "f"(x), "f"(y)); return d;
}
__device__ __forceinline__ float2 unpack2(u64 a) {
    float2 r; asm("mov.b64 {%0, %1}, %2;" : "=f"(r.x), "=f"(r.y) : "l"(a)); return r;
}
__device__ __forceinline__ float hadd2(u64 a) {
    float2 r = unpack2(a); return r.x + r.y;
}
__device__ __forceinline__ float sigf(float x) {
    return __fdividef(1.f, 1.f + __expf(-x));
}
__device__ __forceinline__ float tanh_fast(float x) {
    return 1.f - __fdividef(2.f, __expf(2.f * x) + 1.f);
}

// spin-wait on a device counter (one thread polls, CTA-wide release)
__device__ __forceinline__ void wait_flag(volatile int* flag, int target, int tid) {
    if (tid == 0) {
        while (*flag < target) { __nanosleep(200); }
    }
    __syncthreads();
    __threadfence();   // acquire: order subsequent gmem reads after the flag
}

// ---------------------------------------------------------------------------
// 2-batch LSTM recurrence body. 256 threads, batches (b0, b0+1).
// Thread owns gate rows (tid, 256+tid) for BOTH batches (weights shared).
// Weight cols 0..79 in regs (40 u64/row), cols 80..127 in smem (12 ull2/row).
// Epilogue: tid<128 -> batch0 unit tid; tid>=128 -> batch1 unit tid-128.
// ---------------------------------------------------------------------------
constexpr int REC2_SMEM = 12 * 2 * 256 * 16 + 2 * 128 * 4 + 2 * 256 * 8; // 103,424 B

template<bool WRITE_ALL, bool PUBLISH, bool CONSUME>
__device__ __forceinline__ void rec_body2(const float* __restrict__ Whh,
                                          const float* __restrict__ xp,
                                          float* smbase, int b0)
{
    ulonglong2* wsmq   = (ulonglong2*)smbase;            // [(q*2+row)*256 + tid]
    float*      hbuf0  = smbase + 12 * 2 * 256 * 4;      // 128 floats
    float*      hbuf1  = hbuf0 + 128;                    // 128 floats
    u64*        gat0   = (u64*)(hbuf1 + 128);            // 256 packed pairs
    u64*        gat1   = gat0 + 256;

    const int tid  = threadIdx.x;
    const int rowA = tid;
    const int rowB = 256 + tid;

    // Register weights: cols 0..79 (40 u64 per row)
    u64 wrA[40], wrB[40];
    {
        const u64* pa = (const u64*)(Whh + rowA * IN);
        const u64* pb = (const u64*)(Whh + rowB * IN);
        #pragma unroll
        for (int i = 0; i < 40; i++) { wrA[i] = pa[i]; wrB[i] = pb[i]; }
    }
    // Smem weights: cols 80..127 (12 ulonglong2 per row)
    {
        const ulonglong2* ta = (const ulonglong2*)(Whh + rowA * IN + 80);
        const ulonglong2* tb = (const ulonglong2*)(Whh + rowB * IN + 80);
        #pragma unroll
        for (int q = 0; q < 12; q++) {
            wsmq[(q * 2 + 0) * 256 + tid] = ta[q];
            wsmq[(q * 2 + 1) * 256 + tid] = tb[q];
        }
    }
    if (tid < H) { hbuf0[tid] = 0.f; hbuf1[tid] = 0.f; }
    float cc = 0.f;   // cell state for (batch = tid>>7, unit = tid&127)

    if (CONSUME) wait_flag(&g_xp1_done, NG, tid);   // chunk 0 ready

    const float* xpb0 = xp + (size_t)b0 * G;
    const float* xpb1 = xp + (size_t)(b0 + 1) * G;
    float xa0 = xpb0[rowA], xb0 = xpb0[rowB];
    float xa1 = xpb1[rowA], xb1 = xpb1[rowB];
    const bool tanhB = (tid < 128);
    __syncthreads();

    #pragma unroll 1
    for (int t = 0; t < T; t++) {
        const ulonglong2* h0q = (const ulonglong2*)hbuf0;
        const ulonglong2* h1q = (const ulonglong2*)hbuf1;
        u64 aA0 = 0ull, aA1 = 0ull, aB0 = 0ull, aB1 = 0ull;   // batch0
        u64 cA0 = 0ull, cA1 = 0ull, cB0 = 0ull, cB1 = 0ull;   // batch1
        #pragma unroll
        for (int q = 0; q < 20; q++) {
            const ulonglong2 h0v = h0q[q];
            const ulonglong2 h1v = h1q[q];
            const u64 wa0 = wrA[2 * q], wa1 = wrA[2 * q + 1];
            const u64 wb0 = wrB[2 * q], wb1 = wrB[2 * q + 1];
            aA0 = ffma2(wa0, h0v.x, aA0);
            aA1 = ffma2(wa1, h0v.y, aA1);
            aB0 = ffma2(wb0, h0v.x, aB0);
            aB1 = ffma2(wb1, h0v.y, aB1);
            cA0 = ffma2(wa0, h1v.x, cA0);
            cA1 = ffma2(wa1, h1v.y, cA1);
            cB0 = ffma2(wb0, h1v.x, cB0);
            cB1 = ffma2(wb1, h1v.y, cB1);
        }
        #pragma unroll
        for (int q = 0; q < 12; q++) {
            const ulonglong2 h0v = h0q[20 + q];
            const ulonglong2 h1v = h1q[20 + q];
            const ulonglong2 wa = wsmq[(q * 2 + 0) * 256 + tid];
            const ulonglong2 wb = wsmq[(q * 2 + 1) * 256 + tid];
            aA0 = ffma2(wa.x, h0v.x, aA0);
            aA1 = ffma2(wa.y, h0v.y, aA1);
            aB0 = ffma2(wb.x, h0v.x, aB0);
            aB1 = ffma2(wb.y, h0v.y, aB1);
            cA0 = ffma2(wa.x, h1v.x, cA0);
            cA1 = ffma2(wa.y, h1v.y, cA1);
            cB0 = ffma2(wb.x, h1v.x, cB0);
            cB1 = ffma2(wb.y, h1v.y, cB1);
        }
        const float gA0 = hadd2(aA0) + hadd2(aA1) + xa0;
        const float gB0 = hadd2(aB0) + hadd2(aB1) + xb0;
        const float gA1 = hadd2(cA0) + hadd2(cA1) + xa1;
        const float gB1 = hadd2(cB0) + hadd2(cB1) + xb1;
        const float actA0 = sigf(gA0);
        const float actB0 = tanhB ? tanh_fast(gB0) : sigf(gB0);
        const float actA1 = sigf(gA1);
        const float actB1 = tanhB ? tanh_fast(gB1) : sigf(gB1);
        if (t + 1 < T) {
            if (CONSUME && (((t + 1) & (CH - 1)) == 0)) {
                // entering next chunk: gate the prefetch on its readiness
                wait_flag(&g_xp1_done, NG * (((t + 1) / CH) + 1), tid);
            }
            const size_t off = (size_t)(t + 1) * (B * G);
            xa0 = xpb0[off + rowA]; xb0 = xpb0[off + rowB];
            xa1 = xpb1[off + rowA]; xb1 = xpb1[off + rowB];
        }
        gat0[tid] = pack2(actA0, actB0);
        gat1[tid] = pack2(actA1, actB1);
        __syncthreads();
        {
            const int unit = tid & 127;
            const int bat  = tid >> 7;
            u64*   gsel = bat ? gat1 : gat0;
            float* hsel = bat ? hbuf1 : hbuf0;
            const float2 ig = unpack2(gsel[unit]);          // (i, g)
            const float2 fo = unpack2(gsel[unit + 128]);    // (f, o)
            cc = fo.x * cc + ig.x * ig.y;
            const float h = fo.y * tanh_fast(cc);
            hsel[unit] = h;
            if (WRITE_ALL) {
                g_hs[((size_t)t * B + b0 + bat) * H + unit] = h;
            } else if (t == T - 1) {
                g_hT[(b0 + bat) * H + unit] = h;
            }
        }
        __syncthreads();
        if (PUBLISH && ((t & (CH - 1)) == CH - 1)) {
            __threadfence();          // release this chunk's g_hs
            __syncthreads();
            if (tid == 0) atomicAdd(&g_h0_done, 1);
        }
    }
}

// ---------------------------------------------------------------------------
// GEMM tile compute (64b x 64g, K=128) from smem.
// ---------------------------------------------------------------------------
__device__ __forceinline__ void gemm_tile(const float* Ws, const float* As,
                                          const float* bias, float* outp)
{
    const int tid  = threadIdx.x;
    const int bb   = tid >> 3;
    const int gblk = tid & 7;

    u64 acc[8];
    #pragma unroll
    for (int i = 0; i < 8; i++) acc[i] = 0ull;

    #pragma unroll 8
    for (int k = 0; k < 128; k++) {
        const u64 a0 = pack_dup(As[bb * 136 + k]);
        const u64 a1 = pack_dup(As[(bb + 32) * 136 + k]);
        const ulonglong2* wp = (const ulonglong2*)&Ws[k * 68 + gblk * 8];
        const ulonglong2 wlo = wp[0], whi = wp[1];
        acc[0] = ffma2(wlo.x, a0, acc[0]);
        acc[1] = ffma2(wlo.y, a0, acc[1]);
        acc[2] = ffma2(whi.x, a0, acc[2]);
        acc[3] = ffma2(whi.y, a0, acc[3]);
        acc[4] = ffma2(wlo.x, a1, acc[4]);
        acc[5] = ffma2(wlo.y, a1, acc[5]);
        acc[6] = ffma2(whi.x, a1, acc[6]);
        acc[7] = ffma2(whi.y, a1, acc[7]);
    }

    #pragma unroll
    for (int half = 0; half < 2; half++) {
        const int row = bb + half * 32;
        float4 o0, o1;
        float2 p0 = unpack2(acc[half * 4 + 0]);
        float2 p1 = unpack2(acc[half * 4 + 1]);
        float2 p2 = unpack2(acc[half * 4 + 2]);
        float2 p3 = unpack2(acc[half * 4 + 3]);
        o0.x = p0.x + bias[0]; o0.y = p0.y + bias[1];
        o0.z = p1.x + bias[2]; o0.w = p1.y + bias[3];
        o1.x = p2.x + bias[4]; o1.y = p2.y + bias[5];
        o1.z = p3.x + bias[6]; o1.w = p3.y + bias[7];
        float* op = outp + (size_t)row * G;
        ((float4*)op)[0] = o0;
        ((float4*)op)[1] = o1;
    }
}

// ---------------------------------------------------------------------------
// Kernel: layer-0 input projection GEMM, TT=4. Grid (T/4, 8), 256 threads.
// ---------------------------------------------------------------------------
constexpr int TT = 4;
constexpr int GEMM_SMEM = (128 * 68 + 64 * 136) * 4;   // 69,632 B

__global__ __launch_bounds__(256)
void xproj_gemm0(const float* __restrict__ mapf, const float* __restrict__ pos,
                 const float* __restrict__ Wih,  const float* __restrict__ bih,
                 const float* __restrict__ bhh)
{
    extern __shared__ float sm[];
    float* Ws = sm;               // [128][68] k-major
    float* As = sm + 128 * 68;    // [64][136] row-major

    const int t0  = blockIdx.x * TT;
    const int gc  = blockIdx.y;
    const int tid = threadIdx.x;

    for (int idx = tid; idx < 64 * 128; idx += 256) {
        const int k = idx & 127;
        const int g = idx >> 7;
        Ws[k * 68 + g] = Wih[(gc * 64 + g) * IN + k];
    }

    const int gblk = tid & 7;
    const int gbase = gc * 64 + gblk * 8;
    float bias[8];
    #pragma unroll
    for (int i = 0; i < 8; i++) bias[i] = bih[gbase + i] + bhh[gbase + i];

    for (int tt = 0; tt < TT; tt++) {
        const int t = t0 + tt;
        __syncthreads();
        for (int idx = tid; idx < 64 * 128; idx += 256) {
            const int k = idx & 127;
            const int r = idx >> 7;
            const float v = (k < 126) ? mapf[((size_t)r * T + t) * 126 + k]
                                      : pos[((size_t)r * T + t) * 2 + (k - 126)];
            As[r * 136 + k] = v;
        }
        __syncthreads();
        gemm_tile(Ws, As, bias, g_xp0 + (size_t)t * B * G + gbase);
    }
}

// ---------------------------------------------------------------------------
// TRIPLE-FUSED kernel: rec0 (32 CTAs, 2 batches each) + gemm1 (80 CTAs) +
// rec1 (32 CTAs, 2 batches each) = 144 CTAs at 1 CTA/SM <= 148 SMs ->
// whole grid is wave 1 -> all producers and consumers co-resident.
// Flag chain: rec0 -> g_h0_done -> gemm -> g_xp1_done -> rec1 (acyclic).
// ---------------------------------------------------------------------------
__global__ __launch_bounds__(256, 1)
void fused_pipeline(const float* __restrict__ Whh0,
                    const float* __restrict__ Wih1,
                    const float* __restrict__ bih1,
                    const float* __restrict__ bhh1,
                    const float* __restrict__ Whh1)
{
    extern __shared__ float sm[];
    const int tid = threadIdx.x;
    const int bid = blockIdx.x;

    if (bid < RECC0) {
        rec_body2<true, true, false>(Whh0, g_xp0, sm, 2 * bid);
        return;
    }
    if (bid >= RECC0 + NG) {
        rec_body2<false, false, true>(Whh1, g_xp1, sm, 2 * (bid - RECC0 - NG));
        return;
    }

    // ---- gemm role ----
    const int idx = bid - RECC0;         // 0..NG-1
    const int gc  = idx & 7;
    const int sub = idx >> 3;            // 0..9
    float* Ws = sm;
    float* As = sm + 128 * 68;

    for (int i = tid; i < 64 * 128; i += 256) {
        const int k = i & 127;
        const int g = i >> 7;
        Ws[k * 68 + g] = Wih1[(gc * 64 + g) * IN + k];
    }

    const int gblk = tid & 7;
    const int gbase = gc * 64 + gblk * 8;
    float bias[8];
    #pragma unroll
    for (int i = 0; i < 8; i++) bias[i] = bih1[gbase + i] + bhh1[gbase + i];

    for (int c = 0; c < NCHUNK; c++) {
        wait_flag(&g_h0_done, RECC0 * (c + 1), tid);

        for (int tl = sub; tl < CH; tl += 10) {
            const int t = c * CH + tl;
            __syncthreads();   // protect As from previous tile's readers
            const float4* src = (const float4*)(g_hs + (size_t)t * B * H);
            #pragma unroll
            for (int j = 0; j < 8; j++) {
                const int i4 = tid + j * 256;       // 0..2047
                const int r  = i4 >> 5;
                const int k4 = i4 & 31;
                ((float4*)&As[r * 136 + k4 * 4])[0] = src[i4];
            }
            __syncthreads();
            gemm_tile(Ws, As, bias, g_xp1 + (size_t)t * B * G + gbase);
        }
        __threadfence();          // release this chunk's g_xp1
        __syncthreads();
        if (tid == 0) atomicAdd(&g_xp1_done, 1);
    }
}

// ---------------------------------------------------------------------------
// MLP head: one CTA per batch row, 64 threads.
// ---------------------------------------------------------------------------
__global__ void head_kernel(const float* __restrict__ W1, const float* __restrict__ b1,
                            const float* __restrict__ lng, const float* __restrict__ lnb,
                            const float* __restrict__ W2, const float* __restrict__ b2,
                            float* __restrict__ out)
{
    __shared__ float hb[128];
    __shared__ float red[64];
    __shared__ float bc;
    const int b = blockIdx.x;
    const int j = threadIdx.x;

    hb[j]      = g_hT[b * H + j];
    hb[j + 64] = g_hT[b * H + 64 + j];
    __syncthreads();

    float acc = b1[j];
    #pragma unroll 8
    for (int k = 0; k < H; k++) acc += hb[k] * W1[j * H + k];

    red[j] = acc; __syncthreads();
    if (j == 0) { float s = 0.f; for (int k = 0; k < 64; k++) s += red[k]; bc = s * (1.f / 64.f); }
    __syncthreads();
    const float mu = bc;
    const float d  = acc - mu;

    red[j] = d * d; __syncthreads();
    if (j == 0) { float s = 0.f; for (int k = 0; k < 64; k++) s += red[k]; bc = s * (1.f / 64.f); }
    __syncthreads();
    const float var = bc;

    float v = d * rsqrtf(var + 1e-5f) * lng[j] + lnb[j];
    v = (v >= 0.f) ? v : 0.2f * v;

    red[j] = v * W2[j]; __syncthreads();
    if (j == 0) { float s = 0.f; for (int k = 0; k < 64; k++) s += red[k]; out[b] = s + b2[0]; }
}

// ---------------------------------------------------------------------------
// Launch: reset -> gemm0 -> fused(rec0 || gemm1 || rec1) -> head
// ---------------------------------------------------------------------------
extern "C" void kernel_launch(void* const* d_in, const int* in_sizes, int n_in,
                              void* d_out, int out_size)
{
    const float* mapf = (const float*)d_in[0];
    const float* pos  = (const float*)d_in[1];
    const float* Wih0 = (const float*)d_in[2];
    const float* Whh0 = (const float*)d_in[3];
    const float* bih0 = (const float*)d_in[4];
    const float* bhh0 = (const float*)d_in[5];
    const float* Wih1 = (const float*)d_in[6];
    const float* Whh1 = (const float*)d_in[7];
    const float* bih1 = (const float*)d_in[8];
    const float* bhh1 = (const float*)d_in[9];
    const float* W1   = (const float*)d_in[10];
    const float* b1   = (const float*)d_in[11];
    const float* lng  = (const float*)d_in[12];
    const float* lnb  = (const float*)d_in[13];
    const float* W2   = (const float*)d_in[14];
    const float* b2   = (const float*)d_in[15];
    float* out = (float*)d_out;

    cudaFuncSetAttribute((const void*)xproj_gemm0,
                         cudaFuncAttributeMaxDynamicSharedMemorySize, GEMM_SMEM);
    cudaFuncSetAttribute((const void*)fused_pipeline,
                         cudaFuncAttributeMaxDynamicSharedMemorySize, REC2_SMEM);

    reset_flags<<<1, 1>>>();
    dim3 gg(T / TT, 8);
    xproj_gemm0<<<gg, 256, GEMM_SMEM>>>(mapf, pos, Wih0, bih0, bhh0);
    fused_pipeline<<<RECC0 + NG + RECC1, 256, REC2_SMEM>>>(Whh0, Wih1, bih1, bhh1, Whh1);
    head_kernel<<<B, 64>>>(W1, b1, lng, lnb, W2, b2, out);
}